// round 17
// baseline (speedup 1.0000x reference)
#include <cuda_runtime.h>
#include <cuda_bf16.h>
#include <math.h>
#include <stdint.h>

#define MAXN 100000
#define NPAD 100128            // MAXN rounded up past a 128-row tile
#define PLANEB (NPAD * 128)    // bytes per 64-col (128B-row) plane
#define CAP  128
#define LN_EPS 1e-5

typedef unsigned long long u64;

// ---------------- scratch (static device globals; no allocation) ----------------
__device__ float  g_h1 [(size_t)MAXN * 128];
__device__ float  g_tmp[(size_t)MAXN * 128];
__device__ int    g_cnt[MAXN];
__device__ double g_red[8];
__device__ int    g_csr[(size_t)MAXN * CAP];
// pre-swizzled bf16 images (chunk-major planes of 128B rows)
__device__ __align__(16) unsigned char g_wimgh[8 * 32768];
__device__ __align__(16) unsigned char g_wimgl[8 * 32768];
__device__ __align__(16) unsigned char g_xh[PLANEB];
__device__ __align__(16) unsigned char g_xl[PLANEB];
__device__ __align__(16) unsigned char g_aggh[2 * (size_t)PLANEB];
__device__ __align__(16) unsigned char g_aggl[2 * (size_t)PLANEB];
__device__ __align__(16) unsigned char g_tmph[2 * (size_t)PLANEB];
__device__ __align__(16) unsigned char g_tmpl[2 * (size_t)PLANEB];

// swizzled byte offset within a plane: row r, byte-in-row w (16B-unit XOR)
__device__ __forceinline__ size_t swzoff(int r, int w) {
    return (size_t)r * 128 + (w ^ ((r & 7) << 4));
}

// ---------------- mma/ldmatrix/bulk-copy helpers ----------------
__device__ __forceinline__ uint32_t smem_to_u32(const void* p) {
    uint32_t a;
    asm("{ .reg .u64 t; cvta.to.shared.u64 t, %1; cvt.u32.u64 %0, t; }" : "=r"(a) : "l"(p));
    return a;
}
__device__ __forceinline__ void ldsm_x4(uint32_t (&r)[4], uint32_t addr) {
    asm volatile("ldmatrix.sync.aligned.m8n8.x4.shared.b16 {%0,%1,%2,%3}, [%4];"
                 : "=r"(r[0]), "=r"(r[1]), "=r"(r[2]), "=r"(r[3]) : "r"(addr));
}
__device__ __forceinline__ void ldsm_x2(uint32_t (&r)[2], uint32_t addr) {
    asm volatile("ldmatrix.sync.aligned.m8n8.x2.shared.b16 {%0,%1}, [%2];"
                 : "=r"(r[0]), "=r"(r[1]) : "r"(addr));
}
__device__ __forceinline__ void mma_bf16(float (&c)[4], const uint32_t (&a)[4],
                                         const uint32_t (&b)[2]) {
    asm volatile(
        "mma.sync.aligned.m16n8k16.row.col.f32.bf16.bf16.f32 "
        "{%0,%1,%2,%3}, {%4,%5,%6,%7}, {%8,%9}, {%0,%1,%2,%3};"
        : "+f"(c[0]), "+f"(c[1]), "+f"(c[2]), "+f"(c[3])
        : "r"(a[0]), "r"(a[1]), "r"(a[2]), "r"(a[3]), "r"(b[0]), "r"(b[1]));
}
// 1D bulk copy global->shared with mbarrier completion (sm_90+, not a-gated)
__device__ __forceinline__ void bulkcp(uint32_t dst, const void* src, uint32_t bytes,
                                       uint32_t mbar) {
    asm volatile(
        "cp.async.bulk.shared::cta.global.mbarrier::complete_tx::bytes [%0], [%1], %2, [%3];"
        :: "r"(dst), "l"(src), "r"(bytes), "r"(mbar) : "memory");
}
#define MBARRIER_INIT(addr, cnt) \
    asm volatile("mbarrier.init.shared.b64 [%0], %1;" \
        :: "r"((uint32_t)(addr)), "r"((uint32_t)(cnt)) : "memory")
#define MBARRIER_EXPECT_TX(addr, bytes) \
    asm volatile("mbarrier.arrive.expect_tx.shared.b64 _, [%0], %1;" \
        :: "r"((uint32_t)(addr)), "r"((uint32_t)(bytes)) : "memory")
#define MBARRIER_WAIT_PARITY(mbar_smem_addr, phase_parity) do { \
    uint32_t _mbar = (uint32_t)(mbar_smem_addr); \
    uint32_t _parity = (uint32_t)(phase_parity); \
    uint32_t _done; \
    asm volatile( \
        "{\n\t.reg .pred p;\n\t" \
        "mbarrier.try_wait.parity.acquire.cta.shared::cta.b64 p, [%1], %2;\n\t" \
        "selp.b32 %0, 1, 0, p;\n\t}" \
        : "=r"(_done) : "r"(_mbar), "r"(_parity) : "memory"); \
    if (!_done) { \
        asm volatile( \
            "{\n\t.reg .pred P1;\n\t" \
            "WAIT_LOOP_%=:\n\t" \
            "mbarrier.try_wait.parity.acquire.cta.shared::cta.b64 P1, [%0], %1, 0x989680;\n\t" \
            "@P1 bra.uni WAIT_DONE_%=;\n\t" \
            "bra.uni WAIT_LOOP_%=;\n\t" \
            "WAIT_DONE_%=:\n\t}" \
            :: "r"(_mbar), "r"(_parity) : "memory"); \
    } \
} while(0)

// split two fp32 into packed bf16 hi-pair and lo-pair (low 16 bits = first elem)
__device__ __forceinline__ void split2(float v0, float v1, uint32_t& h, uint32_t& l) {
    __nv_bfloat16 h0 = __float2bfloat16(v0);
    __nv_bfloat16 h1 = __float2bfloat16(v1);
    __nv_bfloat16 l0 = __float2bfloat16(v0 - __bfloat162float(h0));
    __nv_bfloat16 l1 = __float2bfloat16(v1 - __bfloat162float(h1));
    h = (uint32_t)__bfloat16_as_ushort(h0) | ((uint32_t)__bfloat16_as_ushort(h1) << 16);
    l = (uint32_t)__bfloat16_as_ushort(l0) | ((uint32_t)__bfloat16_as_ushort(l1) << 16);
}

// ---------------- merged setup kernel ----------------
__global__ void setup_kernel(const float* __restrict__ x,
                             const float* Wl1, const float* Wr1, const float* Ws1,
                             const float* Wl2, const float* Wr2, const float* Ws2,
                             const float* Wl3, const float* Wr3,
                             int* __restrict__ cnt, double* __restrict__ red,
                             unsigned char* __restrict__ xh, unsigned char* __restrict__ xl,
                             unsigned char* __restrict__ imgh,
                             unsigned char* __restrict__ imgl, int N) {
    int zeroB = (N + 255) >> 8;
    int xB = (N * 32 + 255) >> 8;
    int bid = blockIdx.x;
    int tid = threadIdx.x;
    if (bid < zeroB) {
        int i = bid * 256 + tid;
        if (i < N) cnt[i] = 0;
        if (i < 8) red[i] = 0.0;
    } else if (bid < zeroB + xB) {
        int t = (bid - zeroB) * 256 + tid;
        int row = t >> 5;
        int c2 = t & 31;
        if (row < N) {
            int col = c2 * 2;
            float v0 = (col < 50) ? x[(size_t)row * 50 + col] : 0.0f;
            float v1 = (col + 1 < 50) ? x[(size_t)row * 50 + col + 1] : 0.0f;
            uint32_t h, l;
            split2(v0, v1, h, l);
            size_t off = swzoff(row, c2 * 4);
            *(uint32_t*)(xh + off) = h;
            *(uint32_t*)(xl + off) = l;
        }
    } else {
        int b2 = bid - zeroB - xB;
        int slot = b2 >> 6;
        int idx = (b2 & 63) * 256 + tid;
        const float* W; int K;
        switch (slot) {
            case 0: W = Wl1; K = 50;  break;
            case 1: W = Wr1; K = 50;  break;
            case 2: W = Ws1; K = 50;  break;
            case 3: W = Wl2; K = 128; break;
            case 4: W = Wr2; K = 128; break;
            case 5: W = Ws2; K = 50;  break;
            case 6: W = Wl3; K = 128; break;
            default: W = Wr3; K = 128; break;
        }
        int n = idx >> 7;          // output col 0..127
        int k = idx & 127;         // k 0..127
        float v = (k < K) ? W[(size_t)k * 128 + n] : 0.0f;
        __nv_bfloat16 hb = __float2bfloat16(v);
        __nv_bfloat16 lb = __float2bfloat16(v - __bfloat162float(hb));
        int c = k >> 6, kk = k & 63;
        size_t off = (size_t)slot * 32768 + (size_t)c * 16384 + swzoff(n, kk * 2);
        *(__nv_bfloat16*)(imgh + off) = hb;
        *(__nv_bfloat16*)(imgl + off) = lb;
    }
}

__global__ void fill_kernel(const int* __restrict__ src, const int* __restrict__ dst,
                            int E, int* __restrict__ cnt, int* __restrict__ csr) {
    int e = blockIdx.x * blockDim.x + threadIdx.x;
    if (e >= E) return;
    int d = dst[e];
    int slot = atomicAdd(&cnt[d], 1);
    if (slot < CAP) csr[(size_t)d * CAP + slot] = src[e];
}

// ---------------- CSR mean-aggregation -> swizzled bf16 hi/lo planes ----------------
// warp = (node, column-half)
__global__ void aggregate128_kernel(const float* __restrict__ feat,
                                    const int* __restrict__ csr,
                                    const int* __restrict__ cnt,
                                    unsigned char* __restrict__ mh,
                                    unsigned char* __restrict__ ml, int N) {
    int gw = (blockIdx.x * blockDim.x + threadIdx.x) >> 5;
    int lane = threadIdx.x & 31;
    int node = gw >> 1;
    int half = gw & 1;
    if (node >= N) return;
    int deg = cnt[node];
    int n = deg < CAP ? deg : CAP;
    const int* row = csr + (size_t)node * CAP;
    const float* fb = feat + half * 64 + lane * 2;

    float2 a[8];
    #pragma unroll
    for (int j = 0; j < 8; j++) a[j] = make_float2(0.f, 0.f);
    int e = 0;
    for (; e + 8 <= n; e += 8) {
        int s[8];
        #pragma unroll
        for (int j = 0; j < 8; j++) s[j] = __ldg(&row[e + j]);
        #pragma unroll
        for (int j = 0; j < 8; j++) {
            float2 v = *(const float2*)(fb + (size_t)s[j] * 128);
            a[j].x += v.x; a[j].y += v.y;
        }
    }
    for (; e < n; e++) {
        int s = __ldg(&row[e]);
        float2 v = *(const float2*)(fb + (size_t)s * 128);
        a[0].x += v.x; a[0].y += v.y;
    }
    #pragma unroll
    for (int j = 1; j < 8; j++) { a[0].x += a[j].x; a[0].y += a[j].y; }
    float s = 1.0f / (float)(deg > 1 ? deg : 1);
    uint32_t h, l;
    split2(a[0].x * s, a[0].y * s, h, l);
    size_t off = (size_t)half * PLANEB + swzoff(node, lane * 4);
    *(uint32_t*)(mh + off) = h;
    *(uint32_t*)(ml + off) = l;
}

// D=50 variant: single plane [N][64 cols], zeros for cols 50..63
__global__ void aggregate50_kernel(const float* __restrict__ feat,
                                   const int* __restrict__ csr,
                                   const int* __restrict__ cnt,
                                   unsigned char* __restrict__ mh,
                                   unsigned char* __restrict__ ml, int N) {
    int warp = (blockIdx.x * blockDim.x + threadIdx.x) >> 5;
    int lane = threadIdx.x & 31;
    if (warp >= N) return;
    int deg = cnt[warp];
    float2 r = make_float2(0.f, 0.f);
    if (lane < 25) {
        int n = deg < CAP ? deg : CAP;
        const int* row = csr + (size_t)warp * CAP;
        float2 a[8];
        #pragma unroll
        for (int j = 0; j < 8; j++) a[j] = make_float2(0.f, 0.f);
        int e = 0;
        for (; e + 8 <= n; e += 8) {
            int s[8];
            #pragma unroll
            for (int j = 0; j < 8; j++) s[j] = __ldg(&row[e + j]);
            #pragma unroll
            for (int j = 0; j < 8; j++) {
                float2 v = *(const float2*)(feat + (size_t)s[j] * 50 + lane * 2);
                a[j].x += v.x; a[j].y += v.y;
            }
        }
        for (; e < n; e++) {
            int s = __ldg(&row[e]);
            float2 v = *(const float2*)(feat + (size_t)s * 50 + lane * 2);
            a[0].x += v.x; a[0].y += v.y;
        }
        #pragma unroll
        for (int j = 1; j < 8; j++) { a[0].x += a[j].x; a[0].y += a[j].y; }
        float s = 1.0f / (float)(deg > 1 ? deg : 1);
        r.x = a[0].x * s; r.y = a[0].y * s;
    }
    uint32_t h, l;
    split2(r.x, r.y, h, l);
    size_t off = swzoff(warp, lane * 4);
    *(uint32_t*)(mh + off) = h;
    *(uint32_t*)(ml + off) = l;
}

// ---------------- bulk-copy-pipelined mma.sync GEMM (KC=64, pre-swizzled) --------
// smem: A bufs 2x32KB, B 32KB, mbarriers, reduction scratch
#define SM_AH(b) ((b) * 32768)
#define SM_AL(b) ((b) * 32768 + 16384)
#define SM_BH 65536
#define SM_BL 81920
#define SM_MBAR 98304          // mbarA0 @ +0, mbarA1 @ +8, mbarB @ +16
#define SREDO 98432
#define SMBYTES (98432 + 256)

// EPI 0: + bias, store raw to out, accumulate (sum,sumsq) into redOut
// EPI 1: v = prelu(ln(rawbuf)); out2 = v; out = v + acc; split(out)->outsh/outsl
// EPI 2: v = prelu(ln(rawbuf)); out  = v + addend + acc; split(out)->outsh/outsl
template<int CH1, int CH2, int EPI>
__global__ __launch_bounds__(512, 2)
void gemm_mma(const unsigned char* __restrict__ A1h, const unsigned char* __restrict__ A1l,
              const unsigned char* __restrict__ A2h, const unsigned char* __restrict__ A2l,
              const unsigned char* __restrict__ B1h, const unsigned char* __restrict__ B1l,
              const unsigned char* __restrict__ B2h, const unsigned char* __restrict__ B2l,
              const float* __restrict__ bias,
              float* __restrict__ out, float* __restrict__ out2,
              unsigned char* __restrict__ outsh, unsigned char* __restrict__ outsl,
              const float* __restrict__ rawbuf, const float* __restrict__ addend,
              const float* __restrict__ lnw, const float* __restrict__ lnb,
              const float* __restrict__ alpha,
              const double* __restrict__ redIn, double* __restrict__ redOut,
              int N) {
    extern __shared__ __align__(16) unsigned char sm[];
    uint32_t sb = smem_to_u32(sm);
    int tid = threadIdx.x;
    int lane = tid & 31;
    int warp = tid >> 5;
    int wm = warp >> 2;
    int wn = warp & 3;
    int blockRow = blockIdx.x * 128;

    constexpr int CH = CH1 + CH2;
    size_t arowoff = (size_t)blockRow * 128;

    // issue A-plane bulk copies for chunk cc into buffer buf (thread 0 only)
    auto issue_A = [&](int cc, int buf) {
        const unsigned char *ph, *pl;
        if (cc < CH1) { ph = A1h + (size_t)cc * PLANEB; pl = A1l + (size_t)cc * PLANEB; }
        else          { ph = A2h + (size_t)(cc - CH1) * PLANEB; pl = A2l + (size_t)(cc - CH1) * PLANEB; }
        uint32_t mb = sb + SM_MBAR + buf * 8;
        MBARRIER_EXPECT_TX(mb, 32768u);
        bulkcp(sb + SM_AH(buf), ph + arowoff, 16384u, mb);
        bulkcp(sb + SM_AL(buf), pl + arowoff, 16384u, mb);
    };
    auto issue_B = [&](int cc) {
        const unsigned char *ph, *pl;
        if (cc < CH1) { ph = B1h + (size_t)cc * 16384; pl = B1l + (size_t)cc * 16384; }
        else          { ph = B2h + (size_t)(cc - CH1) * 16384; pl = B2l + (size_t)(cc - CH1) * 16384; }
        uint32_t mb = sb + SM_MBAR + 16;
        MBARRIER_EXPECT_TX(mb, 32768u);
        bulkcp(sb + SM_BH, ph, 16384u, mb);
        bulkcp(sb + SM_BL, pl, 16384u, mb);
    };

    if (tid == 0) {
        MBARRIER_INIT(sb + SM_MBAR + 0, 1);
        MBARRIER_INIT(sb + SM_MBAR + 8, 1);
        MBARRIER_INIT(sb + SM_MBAR + 16, 1);
    }
    __syncthreads();
    if (tid == 0) { issue_A(0, 0); issue_B(0); }

    float acc[2][4][4];
    #pragma unroll
    for (int i = 0; i < 2; i++)
        #pragma unroll
        for (int j = 0; j < 4; j++)
            #pragma unroll
            for (int r = 0; r < 4; r++) acc[i][j][r] = 0.0f;

    int phA0 = 0, phA1 = 0, phB = 0;
    for (int cc = 0; cc < CH; cc++) {
        int buf = cc & 1;
        // prefetch next A into the other buffer (free: last read finished at prior sync)
        if (cc + 1 < CH && tid == 0) issue_A(cc + 1, buf ^ 1);
        // wait current A + B
        if (buf == 0) { MBARRIER_WAIT_PARITY(sb + SM_MBAR + 0, phA0); phA0 ^= 1; }
        else          { MBARRIER_WAIT_PARITY(sb + SM_MBAR + 8, phA1); phA1 ^= 1; }
        MBARRIER_WAIT_PARITY(sb + SM_MBAR + 16, phB); phB ^= 1;

        uint32_t ahb = sb + SM_AH(buf), alb = sb + SM_AL(buf);
        uint32_t bhb = sb + SM_BH, blb = sb + SM_BL;
        #pragma unroll
        for (int ks = 0; ks < 64; ks += 16) {
            uint32_t bh[4][2], bl[4][2];
            #pragma unroll
            for (int ni = 0; ni < 4; ni++) {
                int nrow = wn * 32 + ni * 8 + (lane & 7);
                int bkoff = (ks + ((lane >> 3) & 1) * 8) * 2;
                uint32_t boff = nrow * 128 + (bkoff ^ ((nrow & 7) << 4));
                ldsm_x2(bh[ni], bhb + boff);
                ldsm_x2(bl[ni], blb + boff);
            }
            #pragma unroll
            for (int mi = 0; mi < 2; mi++) {
                int arow = wm * 32 + mi * 16 + (lane & 15);
                int akoff = (ks + (lane >> 4) * 8) * 2;
                uint32_t aoff = arow * 128 + (akoff ^ ((arow & 7) << 4));
                uint32_t ah[4], al[4];
                ldsm_x4(ah, ahb + aoff);
                ldsm_x4(al, alb + aoff);
                #pragma unroll
                for (int ni = 0; ni < 4; ni++) {
                    mma_bf16(acc[mi][ni], ah, bh[ni]);
                    mma_bf16(acc[mi][ni], ah, bl[ni]);
                    mma_bf16(acc[mi][ni], al, bh[ni]);
                }
            }
        }
        __syncthreads();   // all warps done with B (and this A buf) before refill
        if (cc + 1 < CH && tid == 0) issue_B(cc + 1);
    }

    // ---- epilogue ----
    float ls = 0.0f, lq = 0.0f;
    float mu = 0.f, scale = 0.f, aslope = 0.f;
    if constexpr (EPI != 0) {
        double M = (double)N * 128.0;
        double mean = redIn[0] / M;
        double var = redIn[1] / M - mean * mean;
        if (var < 0.0) var = 0.0;
        scale = (float)(1.0 / (sqrt(var) + LN_EPS));
        mu = (float)mean;
        aslope = alpha[0];
    }
    #pragma unroll
    for (int mi = 0; mi < 2; mi++) {
        int rbase = blockRow + wm * 32 + mi * 16 + (lane >> 2);
        #pragma unroll
        for (int ni = 0; ni < 4; ni++) {
            int col = wn * 32 + ni * 8 + (lane & 3) * 2;
            #pragma unroll
            for (int half = 0; half < 2; half++) {
                int r = rbase + half * 8;
                if (r >= N) continue;
                float d0 = acc[mi][ni][half * 2];
                float d1 = acc[mi][ni][half * 2 + 1];
                size_t off = (size_t)r * 128 + col;
                if constexpr (EPI == 0) {
                    float o0 = d0 + bias[col];
                    float o1 = d1 + bias[col + 1];
                    *(float2*)&out[off] = make_float2(o0, o1);
                    ls += o0 + o1;
                    lq += o0 * o0 + o1 * o1;
                } else {
                    float2 rv = *(const float2*)&rawbuf[off];
                    float v0 = (rv.x - mu) * scale * lnw[col] + lnb[col];
                    float v1 = (rv.y - mu) * scale * lnw[col + 1] + lnb[col + 1];
                    v0 = v0 >= 0.f ? v0 : aslope * v0;
                    v1 = v1 >= 0.f ? v1 : aslope * v1;
                    float o0, o1;
                    if constexpr (EPI == 1) {
                        *(float2*)&out2[off] = make_float2(v0, v1);
                        o0 = v0 + d0; o1 = v1 + d1;
                    } else {
                        float2 ad = *(const float2*)&addend[off];
                        o0 = v0 + ad.x + d0; o1 = v1 + ad.y + d1;
                    }
                    *(float2*)&out[off] = make_float2(o0, o1);
                    uint32_t h, l;
                    split2(o0, o1, h, l);
                    int plane = col >> 6;
                    size_t soff = (size_t)plane * PLANEB + swzoff(r, (col & 63) * 2);
                    *(uint32_t*)(outsh + soff) = h;
                    *(uint32_t*)(outsl + soff) = l;
                }
            }
        }
    }

    if constexpr (EPI == 0) {
        #pragma unroll
        for (int off = 16; off > 0; off >>= 1) {
            ls += __shfl_down_sync(0xffffffffu, ls, off);
            lq += __shfl_down_sync(0xffffffffu, lq, off);
        }
        float* sRed = (float*)(sm + SREDO);
        if (lane == 0) { sRed[warp * 2] = ls; sRed[warp * 2 + 1] = lq; }
        __syncthreads();
        if (tid == 0) {
            float S = 0.0f, Q = 0.0f;
            #pragma unroll
            for (int w = 0; w < 16; w++) { S += sRed[w * 2]; Q += sRed[w * 2 + 1]; }
            atomicAdd(&redOut[0], (double)S);
            atomicAdd(&redOut[1], (double)Q);
        }
    }
}

// final LN + PReLU on the output buffer
__global__ void ln_prelu_kernel(float* __restrict__ buf, const double* __restrict__ red,
                                const float* __restrict__ lnw, const float* __restrict__ lnb,
                                const float* __restrict__ alpha, int N) {
    long idx = (long)blockIdx.x * blockDim.x + threadIdx.x;
    long total = (long)N * 32;
    if (idx >= total) return;
    double M = (double)N * 128.0;
    double mean = red[0] / M;
    double var = red[1] / M - mean * mean;
    if (var < 0.0) var = 0.0;
    float sc = (float)(1.0 / (sqrt(var) + LN_EPS));
    float mu = (float)mean;
    float a = alpha[0];
    int c4 = ((int)(idx & 31)) * 4;
    float4 v = ((float4*)buf)[idx];
    float w0 = lnw[c4], w1 = lnw[c4 + 1], w2 = lnw[c4 + 2], w3 = lnw[c4 + 3];
    float b0 = lnb[c4], b1 = lnb[c4 + 1], b2 = lnb[c4 + 2], b3 = lnb[c4 + 3];
    float o0 = (v.x - mu) * sc * w0 + b0; o0 = o0 >= 0.f ? o0 : a * o0;
    float o1 = (v.y - mu) * sc * w1 + b1; o1 = o1 >= 0.f ? o1 : a * o1;
    float o2 = (v.z - mu) * sc * w2 + b2; o2 = o2 >= 0.f ? o2 : a * o2;
    float o3 = (v.w - mu) * sc * w3 + b3; o3 = o3 >= 0.f ? o3 : a * o3;
    ((float4*)buf)[idx] = make_float4(o0, o1, o2, o3);
}

// ---------------- launch ----------------
extern "C" void kernel_launch(void* const* d_in, const int* in_sizes, int n_in,
                              void* d_out, int out_size) {
    const float* x    = (const float*)d_in[0];
    const int*   srcp = (const int*)d_in[1];
    const int*   dstp = (const int*)d_in[2];
    const float* Wl1  = (const float*)d_in[3];
    const float* Wr1  = (const float*)d_in[4];
    const float* b1   = (const float*)d_in[5];
    const float* Wl2  = (const float*)d_in[6];
    const float* Wr2  = (const float*)d_in[7];
    const float* b2   = (const float*)d_in[8];
    const float* Wl3  = (const float*)d_in[9];
    const float* Wr3  = (const float*)d_in[10];
    const float* b3   = (const float*)d_in[11];
    const float* Ws1  = (const float*)d_in[12];
    const float* Ws2  = (const float*)d_in[13];
    const float* lnw1 = (const float*)d_in[14];
    const float* lnb1 = (const float*)d_in[15];
    const float* lnw2 = (const float*)d_in[16];
    const float* lnb2 = (const float*)d_in[17];
    const float* lnw3 = (const float*)d_in[18];
    const float* lnb3 = (const float*)d_in[19];
    const float* a1   = (const float*)d_in[20];
    const float* a2   = (const float*)d_in[21];
    const float* a3   = (const float*)d_in[22];

    int E = in_sizes[1];
    int N = in_sizes[0] / 50;

    float *h1, *tmp;
    double* red;
    int *cnt, *csr;
    unsigned char *imgh, *imgl, *xh, *xl, *aggh, *aggl, *tmph, *tmpl;
    cudaGetSymbolAddress((void**)&h1,   g_h1);
    cudaGetSymbolAddress((void**)&tmp,  g_tmp);
    cudaGetSymbolAddress((void**)&red,  g_red);
    cudaGetSymbolAddress((void**)&cnt,  g_cnt);
    cudaGetSymbolAddress((void**)&csr,  g_csr);
    cudaGetSymbolAddress((void**)&imgh, g_wimgh);
    cudaGetSymbolAddress((void**)&imgl, g_wimgl);
    cudaGetSymbolAddress((void**)&xh,   g_xh);
    cudaGetSymbolAddress((void**)&xl,   g_xl);
    cudaGetSymbolAddress((void**)&aggh, g_aggh);
    cudaGetSymbolAddress((void**)&aggl, g_aggl);
    cudaGetSymbolAddress((void**)&tmph, g_tmph);
    cudaGetSymbolAddress((void**)&tmpl, g_tmpl);

    float* out = (float*)d_out;

    int gemmGrid = (N + 127) / 128;
    int aggGrid = (N + 7) / 8;
    int agg2Grid = (2 * N + 7) / 8;
    int zeroB = (N + 255) / 256;
    int xB = (N * 32 + 255) / 256;
    int setupGrid = zeroB + xB + 512;

    cudaFuncSetAttribute(gemm_mma<1, 1, 0>, cudaFuncAttributeMaxDynamicSharedMemorySize, SMBYTES);
    cudaFuncSetAttribute(gemm_mma<0, 1, 1>, cudaFuncAttributeMaxDynamicSharedMemorySize, SMBYTES);
    cudaFuncSetAttribute(gemm_mma<2, 2, 0>, cudaFuncAttributeMaxDynamicSharedMemorySize, SMBYTES);
    cudaFuncSetAttribute(gemm_mma<0, 1, 2>, cudaFuncAttributeMaxDynamicSharedMemorySize, SMBYTES);

    // launch 0: merged setup (zero + x-split + weight images)
    setup_kernel<<<setupGrid, 256>>>(x, Wl1, Wr1, Ws1, Wl2, Wr2, Ws2, Wl3, Wr3,
                                     cnt, red, xh, xl, imgh, imgl, N);
    // launch 1: CSR fill
    fill_kernel<<<(E + 255) / 256, 256>>>(srcp, dstp, E, cnt, csr);
    // launch 2: layer-1 aggregation
    aggregate50_kernel<<<aggGrid, 256>>>(x, csr, cnt, aggh, aggl, N);
    // launch 3: layer-1 GEMM  h1raw = mean@Wl1 + x@Wr1 + b1
    gemm_mma<1, 1, 0><<<gemmGrid, 512, SMBYTES>>>(
        aggh, aggl, xh, xl,
        imgh + 0 * 32768, imgl + 0 * 32768, imgh + 1 * 32768, imgl + 1 * 32768,
        b1, h1,
        nullptr, nullptr, nullptr, nullptr, nullptr, nullptr, nullptr, nullptr, nullptr,
        red + 0, N);
    // launch 4: h1 := prelu(ln(h1raw)); tmp := h1n + x@Ws1 (+ split planes)
    gemm_mma<0, 1, 1><<<gemmGrid, 512, SMBYTES>>>(
        nullptr, nullptr, xh, xl,
        nullptr, nullptr, imgh + 2 * 32768, imgl + 2 * 32768,
        nullptr, tmp, h1, tmph, tmpl, h1, nullptr,
        lnw1, lnb1, a1, red + 0, nullptr, N);
    // layer 2
    aggregate128_kernel<<<agg2Grid, 256>>>(tmp, csr, cnt, aggh, aggl, N);
    gemm_mma<2, 2, 0><<<gemmGrid, 512, SMBYTES>>>(
        aggh, aggl, tmph, tmpl,
        imgh + 3 * 32768, imgl + 3 * 32768, imgh + 4 * 32768, imgl + 4 * 32768,
        b2, tmp,
        nullptr, nullptr, nullptr, nullptr, nullptr, nullptr, nullptr, nullptr, nullptr,
        red + 2, N);
    gemm_mma<0, 1, 2><<<gemmGrid, 512, SMBYTES>>>(
        nullptr, nullptr, xh, xl,
        nullptr, nullptr, imgh + 5 * 32768, imgl + 5 * 32768,
        nullptr, tmp, nullptr, tmph, tmpl, tmp, h1,
        lnw2, lnb2, a2, red + 2, nullptr, N);
    // layer 3
    aggregate128_kernel<<<agg2Grid, 256>>>(tmp, csr, cnt, aggh, aggl, N);
    gemm_mma<2, 2, 0><<<gemmGrid, 512, SMBYTES>>>(
        aggh, aggl, tmph, tmpl,
        imgh + 6 * 32768, imgl + 6 * 32768, imgh + 7 * 32768, imgl + 7 * 32768,
        b3, out,
        nullptr, nullptr, nullptr, nullptr, nullptr, nullptr, nullptr, nullptr, nullptr,
        red + 4, N);
    ln_prelu_kernel<<<(int)(((long)N * 32 + 255) / 256), 256>>>(out, red + 4,
                                                                lnw3, lnb3, a3, N);
}